// round 7
// baseline (speedup 1.0000x reference)
#include <cuda_runtime.h>
#include <cuda_bf16.h>
#include <math.h>
#include <stdint.h>

#define Bg 8
#define Nn 20000
#define Eg 320000
#define Cc 128
#define Dd 64
#define CAP 96
#define NROW (Bg*Nn)

// ---------------- device scratch ----------------
__device__ int   g_cnt[NROW];
__device__ int   g_adj[(size_t)NROW*CAP];
__device__ int   g_idx[Nn];
__device__ float g_init[Nn*Dd];
__device__ float g_omega[(size_t)NROW*256];
__device__ __nv_bfloat16 g_w1hi[512*256];
__device__ __nv_bfloat16 g_w1lo[512*256];
__device__ __nv_bfloat16 g_w2hi[256*512];
__device__ __nv_bfloat16 g_w2lo[256*512];

// ---------------- graph kernels (unchanged, proven) ----------------
__global__ void k_zero_cnt(){
    int i = blockIdx.x*blockDim.x + threadIdx.x;
    if (i < NROW) g_cnt[i] = 0;
}
__global__ void k_build(const int* __restrict__ edges){
    int i = blockIdx.x*blockDim.x + threadIdx.x;
    if (i >= Bg*Eg) return;
    int b = i / Eg, e = i % Eg;
    const int* eb = edges + (size_t)b*2*Eg;
    int row = b*Nn + eb[e];
    int c = eb[Eg + e];
    int slot = atomicAdd(&g_cnt[row], 1);
    if (slot < CAP) g_adj[(size_t)row*CAP + slot] = c;
}
__global__ void k_argmax(const float* __restrict__ poh){
    int n = blockIdx.x*blockDim.x + threadIdx.x;
    if (n >= Nn) return;
    float best = poh[n]; int bi = 0;
    #pragma unroll 4
    for (int c = 1; c < Cc; c++){
        float v = poh[(size_t)c*Nn + n];
        if (v > best){ best = v; bi = c; }
    }
    g_idx[n] = bi;
}
__global__ void k_gather(const float* __restrict__ emb){
    int i = blockIdx.x*blockDim.x + threadIdx.x;
    if (i >= Nn*16) return;
    int n = i >> 4, l = i & 15;
    float4 v = *(const float4*)(emb + (size_t)g_idx[n]*Dd + l*4);
    *(float4*)(g_init + (size_t)n*Dd + l*4) = v;
}
__global__ void k_hop(int hop){
    int gid = blockIdx.x*blockDim.x + threadIdx.x;
    int row = gid >> 4, lane = gid & 15;
    if (row >= NROW) return;
    int b = row / Nn;
    const float* src; int rs;
    if (hop == 1){ src = g_init + lane*4; rs = Dd; }
    else         { src = g_omega + (size_t)b*Nn*256 + (hop-2)*Dd + lane*4; rs = 256; }
    int cnt = g_cnt[row]; if (cnt > CAP) cnt = CAP;
    const int* adj = g_adj + (size_t)row*CAP;
    float4 s0 = make_float4(0.f,0.f,0.f,0.f), s1 = make_float4(0.f,0.f,0.f,0.f);
    int j = 0;
    for (; j + 2 <= cnt; j += 2){
        int c0 = adj[j], c1 = adj[j+1];
        float4 v0 = *(const float4*)(src + (size_t)c0*rs);
        float4 v1 = *(const float4*)(src + (size_t)c1*rs);
        s0.x += v0.x; s0.y += v0.y; s0.z += v0.z; s0.w += v0.w;
        s1.x += v1.x; s1.y += v1.y; s1.z += v1.z; s1.w += v1.w;
    }
    if (j < cnt){
        float4 v = *(const float4*)(src + (size_t)adj[j]*rs);
        s0.x += v.x; s0.y += v.y; s0.z += v.z; s0.w += v.w;
    }
    float4 r = make_float4(s0.x+s1.x, s0.y+s1.y, s0.z+s1.z, s0.w+s1.w);
    *(float4*)(g_omega + (size_t)row*256 + (hop-1)*Dd + lane*4) = r;
}

// ---------------- weight split/blocking (unchanged) ----------------
__global__ void k_convW1(const float* __restrict__ W1){
    int i = blockIdx.x*256 + threadIdx.x;
    if (i >= 256*512) return;
    int k = i >> 9, n = i & 511;
    int d = k & 63, h = k >> 6;
    float v = W1[(size_t)(d*4 + h)*512 + n];
    __nv_bfloat16 hb = __float2bfloat16(v);
    float lo = v - __bfloat162float(hb);
    int nc = n >> 8, nn = n & 255, kc = k >> 4, kk = k & 15;
    int off = ((nc*16 + kc)*256 + nn)*16 + kk;
    g_w1hi[off] = hb; g_w1lo[off] = __float2bfloat16(lo);
}
__global__ void k_convW2(const float* __restrict__ W2){
    int i = blockIdx.x*256 + threadIdx.x;
    if (i >= 512*256) return;
    int k = i >> 8, n = i & 255;
    float v = W2[(size_t)k*256 + n];
    __nv_bfloat16 hb = __float2bfloat16(v);
    float lo = v - __bfloat162float(hb);
    int kc = k >> 4, kk = k & 15;
    int off = (kc*256 + n)*16 + kk;
    g_w2hi[off] = hb; g_w2lo[off] = __float2bfloat16(lo);
}

// ---------------- fused MLP (cp.async pipeline, fused GEMM1) ----------------
#define AST2 264
#define XST2 520
#define OFF_AH 0
#define OFF_AL 33792
#define OFF_XL 0            // overlays A region after GEMM1 (66,560 <= 67,584)
#define OFF_XH 67584
#define OFF_B  134144       // 2 stages x 32KB
#define OFF_SC 199680
#define SMEM_TOTAL 202752

__device__ __forceinline__ uint32_t smem_u32(const void* p){
    uint32_t a;
    asm("{ .reg .u64 t; cvta.to.shared.u64 t, %1; cvt.u32.u64 %0, t; }" : "=r"(a) : "l"(p));
    return a;
}
__device__ __forceinline__ void cpa16(uint32_t dst, const void* src){
    asm volatile("cp.async.cg.shared.global [%0], [%1], 16;" :: "r"(dst), "l"(src));
}
#define CP_COMMIT() asm volatile("cp.async.commit_group;" ::: "memory")
#define CP_WAIT0()  asm volatile("cp.async.wait_group 0;" ::: "memory")

__device__ __forceinline__ void ldmx4(unsigned* r, uint32_t addr){
    asm volatile("ldmatrix.sync.aligned.m8n8.x4.shared.b16 {%0,%1,%2,%3}, [%4];"
        : "=r"(r[0]), "=r"(r[1]), "=r"(r[2]), "=r"(r[3]) : "r"(addr));
}
__device__ __forceinline__ void mma_bf16(float* d, const unsigned* a, unsigned b0, unsigned b1){
    asm volatile(
      "mma.sync.aligned.m16n8k16.row.col.f32.bf16.bf16.f32 "
      "{%0,%1,%2,%3},{%4,%5,%6,%7},{%8,%9},{%0,%1,%2,%3};"
      : "+f"(d[0]), "+f"(d[1]), "+f"(d[2]), "+f"(d[3])
      : "r"(a[0]), "r"(a[1]), "r"(a[2]), "r"(a[3]), "r"(b0), "r"(b1));
}
__device__ __forceinline__ void split2(float x, float y, unsigned &hi, unsigned &lo){
    __nv_bfloat162 h = __floats2bfloat162_rn(x, y);
    float lx = x - __bfloat162float(__low2bfloat16(h));
    float ly = y - __bfloat162float(__high2bfloat16(h));
    __nv_bfloat162 l = __floats2bfloat162_rn(lx, ly);
    hi = *reinterpret_cast<unsigned*>(&h);
    lo = *reinterpret_cast<unsigned*>(&l);
}
__device__ __forceinline__ float2 rec2(unsigned h, unsigned l){
    __nv_bfloat162 hb = *reinterpret_cast<__nv_bfloat162*>(&h);
    __nv_bfloat162 lb = *reinterpret_cast<__nv_bfloat162*>(&l);
    return make_float2(__low2float(hb) + __low2float(lb),
                       __high2float(hb) + __high2float(lb));
}
// swizzled B smem offset for (global n row, k-half)
__device__ __forceinline__ uint32_t boff(int n, int kh){
    return (uint32_t)(n*32 + ((kh ^ ((n>>2)&1))<<4));
}

// stage: hi half0 8KB | hi half1 8KB | lo half0 8KB | lo half1 8KB  (32KB)
__device__ __forceinline__ void issue_b512(uint32_t base,
    const __nv_bfloat16* h0, const __nv_bfloat16* h1,
    const __nv_bfloat16* l0, const __nv_bfloat16* l1, int tid)
{
    #pragma unroll
    for (int r = 0; r < 2; r++){
        int u = tid + r*256;
        int n = u >> 1, kh = u & 1;
        uint32_t o = boff(n, kh);
        cpa16(base + o,         (const char*)h0 + (size_t)u*16);
        cpa16(base + 8192 + o,  (const char*)h1 + (size_t)u*16);
        cpa16(base + 16384 + o, (const char*)l0 + (size_t)u*16);
        cpa16(base + 24576 + o, (const char*)l1 + (size_t)u*16);
    }
    CP_COMMIT();
}
// GEMM2 stage: hi 8KB @ +0, lo 8KB @ +16384 (consistent lo offset)
__device__ __forceinline__ void issue_b256(uint32_t base,
    const __nv_bfloat16* h0, const __nv_bfloat16* l0, int tid)
{
    #pragma unroll
    for (int r = 0; r < 2; r++){
        int u = tid + r*256;
        int n = u >> 1, kh = u & 1;
        uint32_t o = boff(n, kh);
        cpa16(base + o,         (const char*)h0 + (size_t)u*16);
        cpa16(base + 16384 + o, (const char*)l0 + (size_t)u*16);
    }
    CP_COMMIT();
}

__global__ void __launch_bounds__(256,1) k_mlp(
    const float* __restrict__ b1v, const float* __restrict__ gamma,
    const float* __restrict__ beta, const float* __restrict__ b2v,
    float* __restrict__ out)
{
    extern __shared__ char sm[];
    uint32_t smb = smem_u32(sm);
    float* SC = (float*)(sm + OFF_SC);

    int tid = threadIdx.x;
    int lane = tid & 31, w = tid >> 5;
    int gid = lane >> 2, tig = lane & 3;
    int rowBase = blockIdx.x * 64;

    int arow = lane & 15, akh = (lane >> 4) * 8;
    int brow = (lane & 7) + ((lane >> 4) & 1) * 8;
    int bkh  = (lane >> 3) & 1;
    // per-lane B smem offsets for 4 jj-groups (16 n each): jj 0,1 -> half0; 2,3 -> half1
    uint32_t bofs[4];
    #pragma unroll
    for (int jj = 0; jj < 4; jj++){
        int n = (jj >> 1)*256 + w*32 + (jj & 1)*16 + brow;
        bofs[jj] = boff(n, bkh);
    }

    // ---- load A tile [64][256], split fp32 -> bf16 hi/lo into smem ----
    for (int i = tid; i < 4096; i += 256){
        int r = i >> 6, c = (i & 63)*4;
        float4 v = *(const float4*)(g_omega + (size_t)(rowBase + r)*256 + c);
        unsigned h0, l0, h1, l1;
        split2(v.x, v.y, h0, l0);
        split2(v.z, v.w, h1, l1);
        *(uint2*)(sm + OFF_AH + (size_t)(r*AST2 + c)*2) = make_uint2(h0, h1);
        *(uint2*)(sm + OFF_AL + (size_t)(r*AST2 + c)*2) = make_uint2(l0, l1);
    }

    // ---- GEMM1 (fused both N-halves): acc[4 m][8 j][4], K=256, 16 k-steps ----
    float acc[4][8][4];
    #pragma unroll
    for (int i = 0; i < 4; i++)
        #pragma unroll
        for (int j = 0; j < 8; j++)
            #pragma unroll
            for (int q = 0; q < 4; q++) acc[i][j][q] = 0.f;

    issue_b512(smb + OFF_B, g_w1hi, g_w1hi + 16*4096, g_w1lo, g_w1lo + 16*4096, tid);

    for (int kc = 0; kc < 16; kc++){
        CP_WAIT0();
        __syncthreads();
        if (kc + 1 < 16){
            uint32_t nb = smb + OFF_B + ((kc+1)&1)*32768;
            issue_b512(nb, g_w1hi + (size_t)(kc+1)*4096, g_w1hi + (size_t)(16+kc+1)*4096,
                           g_w1lo + (size_t)(kc+1)*4096, g_w1lo + (size_t)(16+kc+1)*4096, tid);
        }
        uint32_t bb = smb + OFF_B + (kc&1)*32768;
        unsigned ah[4][4], al[4][4];
        uint32_t abase = (uint32_t)((arow*AST2 + kc*16 + akh)*2);
        #pragma unroll
        for (int i = 0; i < 4; i++){
            ldmx4(ah[i], smb + OFF_AH + abase + (uint32_t)(i*16*AST2*2));
            ldmx4(al[i], smb + OFF_AL + abase + (uint32_t)(i*16*AST2*2));
        }
        #pragma unroll
        for (int jh = 0; jh < 2; jh++){
            unsigned bh[2][4], bl[2][4];
            #pragma unroll
            for (int q = 0; q < 2; q++){
                int jj = jh*2 + q;
                ldmx4(bh[q], bb + bofs[jj]);
                ldmx4(bl[q], bb + 16384 + bofs[jj]);
            }
            #pragma unroll
            for (int t = 0; t < 3; t++){
                #pragma unroll
                for (int jq = 0; jq < 4; jq++){
                    unsigned b0 = (t == 1) ? bl[jq>>1][(jq&1)*2]   : bh[jq>>1][(jq&1)*2];
                    unsigned b1 = (t == 1) ? bl[jq>>1][(jq&1)*2+1] : bh[jq>>1][(jq&1)*2+1];
                    int j = jh*4 + jq;
                    #pragma unroll
                    for (int i = 0; i < 4; i++)
                        mma_bf16(acc[i][j], (t == 2) ? al[i] : ah[i], b0, b1);
                }
            }
        }
    }
    __syncthreads();   // all A reads done; XL may now overlay A region

    // ---- GEMM1 epilogue: + b1, split, store X hi/lo to smem ----
    #pragma unroll
    for (int j = 0; j < 8; j++){
        int col = (j >> 2)*256 + w*32 + (j & 3)*8 + tig*2;
        float ba = __ldg(b1v + col), bb2 = __ldg(b1v + col + 1);
        #pragma unroll
        for (int i = 0; i < 4; i++){
            int r = i*16 + gid;
            unsigned h, l;
            split2(acc[i][j][0] + ba, acc[i][j][1] + bb2, h, l);
            *(unsigned*)(sm + OFF_XH + (size_t)(r*XST2 + col)*2) = h;
            *(unsigned*)(sm + OFF_XL + (size_t)(r*XST2 + col)*2) = l;
            split2(acc[i][j][2] + ba, acc[i][j][3] + bb2, h, l);
            *(unsigned*)(sm + OFF_XH + (size_t)((r+8)*XST2 + col)*2) = h;
            *(unsigned*)(sm + OFF_XL + (size_t)((r+8)*XST2 + col)*2) = l;
        }
    }
    __syncthreads();

    // prefetch GEMM2 stage 0 (overlaps LN)
    issue_b256(smb + OFF_B, g_w2hi, g_w2lo, tid);

    // ---- LayerNorm + GELU on X (hi/lo reconstruct, in place) ----
    {
        int r = tid & 63, q = tid >> 6;
        char* xh = sm + OFF_XH + (size_t)(r*XST2 + q*128)*2;
        char* xl = sm + OFF_XL + (size_t)(r*XST2 + q*128)*2;
        float s = 0.f, s2 = 0.f;
        #pragma unroll
        for (int i = 0; i < 16; i++){
            uint4 hv = *(uint4*)(xh + i*16);
            uint4 lv = *(uint4*)(xl + i*16);
            float2 e;
            e = rec2(hv.x, lv.x); s += e.x + e.y; s2 += e.x*e.x + e.y*e.y;
            e = rec2(hv.y, lv.y); s += e.x + e.y; s2 += e.x*e.x + e.y*e.y;
            e = rec2(hv.z, lv.z); s += e.x + e.y; s2 += e.x*e.x + e.y*e.y;
            e = rec2(hv.w, lv.w); s += e.x + e.y; s2 += e.x*e.x + e.y*e.y;
        }
        SC[q*64 + r] = s; SC[256 + q*64 + r] = s2;
        __syncthreads();
        if (tid < 64){
            float S  = SC[tid] + SC[64+tid] + SC[128+tid] + SC[192+tid];
            float S2 = SC[256+tid] + SC[320+tid] + SC[384+tid] + SC[448+tid];
            float mu  = S * (1.f/512.f);
            float var = S2 * (1.f/512.f) - mu*mu;
            SC[512 + tid] = mu;
            SC[576 + tid] = rsqrtf(var + 1e-5f);
        }
        __syncthreads();
        float mu = SC[512 + r], rsg = SC[576 + r];
        #pragma unroll
        for (int i = 0; i < 16; i++){
            uint4 hv = *(uint4*)(xh + i*16);
            uint4 lv = *(uint4*)(xl + i*16);
            unsigned hw[4], lw[4];
            unsigned* hvp = (unsigned*)&hv;
            unsigned* lvp = (unsigned*)&lv;
            #pragma unroll
            for (int t = 0; t < 4; t++){
                float2 e = rec2(hvp[t], lvp[t]);
                int c = q*128 + i*8 + t*2;
                float g0 = __ldg(gamma + c), g1 = __ldg(gamma + c + 1);
                float be0 = __ldg(beta + c), be1 = __ldg(beta + c + 1);
                e.x = (e.x - mu)*rsg*g0 + be0;
                e.y = (e.y - mu)*rsg*g1 + be1;
                e.x = 0.5f*e.x*(1.f + erff(e.x*0.70710678118654752f));
                e.y = 0.5f*e.y*(1.f + erff(e.y*0.70710678118654752f));
                split2(e.x, e.y, hw[t], lw[t]);
            }
            *(uint4*)(xh + i*16) = make_uint4(hw[0], hw[1], hw[2], hw[3]);
            *(uint4*)(xl + i*16) = make_uint4(lw[0], lw[1], lw[2], lw[3]);
        }
    }

    // ---- GEMM2: OUT = X @ W2, N=256, K=512, 32 k-steps ----
    float acc2[4][4][4];
    #pragma unroll
    for (int i = 0; i < 4; i++)
        #pragma unroll
        for (int j = 0; j < 4; j++)
            #pragma unroll
            for (int q = 0; q < 4; q++) acc2[i][j][q] = 0.f;

    for (int kc = 0; kc < 32; kc++){
        CP_WAIT0();
        __syncthreads();
        if (kc + 1 < 32){
            uint32_t nb = smb + OFF_B + ((kc+1)&1)*32768;
            issue_b256(nb, g_w2hi + (size_t)(kc+1)*4096, g_w2lo + (size_t)(kc+1)*4096, tid);
        }
        uint32_t bb = smb + OFF_B + (kc&1)*32768;
        unsigned ah[4][4], al[4][4];
        uint32_t abase = (uint32_t)((arow*XST2 + kc*16 + akh)*2);
        #pragma unroll
        for (int i = 0; i < 4; i++){
            ldmx4(ah[i], smb + OFF_XH + abase + (uint32_t)(i*16*XST2*2));
            ldmx4(al[i], smb + OFF_XL + abase + (uint32_t)(i*16*XST2*2));
        }
        unsigned bh[2][4], bl[2][4];
        #pragma unroll
        for (int q = 0; q < 2; q++){
            ldmx4(bh[q], bb + bofs[q]);
            ldmx4(bl[q], bb + 16384 + bofs[q]);
        }
        #pragma unroll
        for (int t = 0; t < 3; t++){
            #pragma unroll
            for (int j = 0; j < 4; j++){
                unsigned b0 = (t == 1) ? bl[j>>1][(j&1)*2]   : bh[j>>1][(j&1)*2];
                unsigned b1 = (t == 1) ? bl[j>>1][(j&1)*2+1] : bh[j>>1][(j&1)*2+1];
                #pragma unroll
                for (int i = 0; i < 4; i++)
                    mma_bf16(acc2[i][j], (t == 2) ? al[i] : ah[i], b0, b1);
            }
        }
    }

    // ---- GEMM2 epilogue: + b2, write out ----
    #pragma unroll
    for (int j = 0; j < 4; j++){
        int col = w*32 + j*8 + tig*2;
        float ba = __ldg(b2v + col), bb2 = __ldg(b2v + col + 1);
        #pragma unroll
        for (int i = 0; i < 4; i++){
            int r = i*16 + gid;
            *(float2*)(out + (size_t)(rowBase + r)*256 + col)     = make_float2(acc2[i][j][0] + ba, acc2[i][j][1] + bb2);
            *(float2*)(out + (size_t)(rowBase + r + 8)*256 + col) = make_float2(acc2[i][j][2] + ba, acc2[i][j][3] + bb2);
        }
    }
}

// ---------------- launch ----------------
extern "C" void kernel_launch(void* const* d_in, const int* in_sizes, int n_in,
                              void* d_out, int out_size)
{
    const int* edges = (const int*)d_in[0];
    int p = (in_sizes[1] <= 2) ? 2 : 1;
    const float* poh   = (const float*)d_in[p+0];
    const float* emb   = (const float*)d_in[p+1];
    const float* W1    = (const float*)d_in[p+2];
    const float* b1    = (const float*)d_in[p+3];
    const float* gamma = (const float*)d_in[p+4];
    const float* beta  = (const float*)d_in[p+5];
    const float* W2    = (const float*)d_in[p+6];
    const float* b2    = (const float*)d_in[p+7];
    float* out = (float*)d_out;

    cudaFuncSetAttribute(k_mlp, cudaFuncAttributeMaxDynamicSharedMemorySize, SMEM_TOTAL);

    k_zero_cnt<<<(NROW + 255)/256, 256>>>();
    k_build  <<<(Bg*Eg + 255)/256, 256>>>(edges);
    k_argmax <<<(Nn + 255)/256, 256>>>(poh);
    k_gather <<<(Nn*16 + 255)/256, 256>>>(emb);
    k_convW1 <<<512, 256>>>(W1);
    k_convW2 <<<512, 256>>>(W2);
    for (int h = 1; h <= 4; h++)
        k_hop<<<(NROW*16 + 255)/256, 256>>>(h);
    k_mlp<<<NROW/64, 256, SMEM_TOTAL>>>(b1, gamma, beta, b2, out);
}

// round 8
// speedup vs baseline: 1.0130x; 1.0130x over previous
#include <cuda_runtime.h>
#include <cuda_bf16.h>
#include <math.h>
#include <stdint.h>

#define Bg 8
#define Nn 20000
#define Eg 320000
#define Cc 128
#define Dd 64
#define CAP 96
#define NROW (Bg*Nn)

// ---------------- device scratch ----------------
__device__ int   g_cnt[NROW];
__device__ int   g_adj[(size_t)NROW*CAP];
__device__ int   g_idx[Nn];
__device__ float g_init[Nn*Dd];
__device__ float g_omega[(size_t)NROW*256];
__device__ __nv_bfloat16 g_w1hi[512*256];
__device__ __nv_bfloat16 g_w1lo[512*256];
__device__ __nv_bfloat16 g_w2hi[256*512];
__device__ __nv_bfloat16 g_w2lo[256*512];

// ---------------- graph kernels ----------------
__global__ void k_zero_cnt(){
    int i = blockIdx.x*blockDim.x + threadIdx.x;
    if (i < NROW) g_cnt[i] = 0;
}
__global__ void k_build(const int* __restrict__ edges){
    int i = blockIdx.x*blockDim.x + threadIdx.x;
    if (i >= Bg*Eg) return;
    int b = i / Eg, e = i % Eg;
    const int* eb = edges + (size_t)b*2*Eg;
    int row = b*Nn + eb[e];
    int c = eb[Eg + e];
    int slot = atomicAdd(&g_cnt[row], 1);
    if (slot < CAP) g_adj[(size_t)row*CAP + slot] = c;
}
__global__ void k_argmax(const float* __restrict__ poh){
    int n = blockIdx.x*blockDim.x + threadIdx.x;
    if (n >= Nn) return;
    float best = poh[n]; int bi = 0;
    #pragma unroll 4
    for (int c = 1; c < Cc; c++){
        float v = poh[(size_t)c*Nn + n];
        if (v > best){ best = v; bi = c; }
    }
    g_idx[n] = bi;
}
__global__ void k_gather(const float* __restrict__ emb){
    int i = blockIdx.x*blockDim.x + threadIdx.x;
    if (i >= Nn*16) return;
    int n = i >> 4, l = i & 15;
    float4 v = *(const float4*)(emb + (size_t)g_idx[n]*Dd + l*4);
    *(float4*)(g_init + (size_t)n*Dd + l*4) = v;
}
// hop: one 16-lane group per output row; 4-deep unrolled gather for MLP
__global__ void k_hop(int hop){
    int gid = blockIdx.x*blockDim.x + threadIdx.x;
    int row = gid >> 4, lane = gid & 15;
    if (row >= NROW) return;
    int b = row / Nn;
    const float* src; int rs;
    if (hop == 1){ src = g_init + lane*4; rs = Dd; }
    else         { src = g_omega + (size_t)b*Nn*256 + (hop-2)*Dd + lane*4; rs = 256; }
    int cnt = __ldg(&g_cnt[row]); if (cnt > CAP) cnt = CAP;
    const int* adj = g_adj + (size_t)row*CAP;
    float4 s0 = make_float4(0.f,0.f,0.f,0.f), s1 = make_float4(0.f,0.f,0.f,0.f);
    float4 s2 = make_float4(0.f,0.f,0.f,0.f), s3 = make_float4(0.f,0.f,0.f,0.f);
    int j = 0;
    for (; j + 4 <= cnt; j += 4){
        int c0 = __ldg(adj + j),     c1 = __ldg(adj + j + 1);
        int c2 = __ldg(adj + j + 2), c3 = __ldg(adj + j + 3);
        float4 v0 = *(const float4*)(src + (size_t)c0*rs);
        float4 v1 = *(const float4*)(src + (size_t)c1*rs);
        float4 v2 = *(const float4*)(src + (size_t)c2*rs);
        float4 v3 = *(const float4*)(src + (size_t)c3*rs);
        s0.x += v0.x; s0.y += v0.y; s0.z += v0.z; s0.w += v0.w;
        s1.x += v1.x; s1.y += v1.y; s1.z += v1.z; s1.w += v1.w;
        s2.x += v2.x; s2.y += v2.y; s2.z += v2.z; s2.w += v2.w;
        s3.x += v3.x; s3.y += v3.y; s3.z += v3.z; s3.w += v3.w;
    }
    for (; j < cnt; j++){
        float4 v = *(const float4*)(src + (size_t)__ldg(adj + j)*rs);
        s0.x += v.x; s0.y += v.y; s0.z += v.z; s0.w += v.w;
    }
    float4 r = make_float4(s0.x+s1.x+s2.x+s3.x, s0.y+s1.y+s2.y+s3.y,
                           s0.z+s1.z+s2.z+s3.z, s0.w+s1.w+s2.w+s3.w);
    *(float4*)(g_omega + (size_t)row*256 + (hop-1)*Dd + lane*4) = r;
}

// ---------------- weight split/blocking ----------------
__global__ void k_convW1(const float* __restrict__ W1){
    int i = blockIdx.x*256 + threadIdx.x;
    if (i >= 256*512) return;
    int k = i >> 9, n = i & 511;
    int d = k & 63, h = k >> 6;
    float v = W1[(size_t)(d*4 + h)*512 + n];
    __nv_bfloat16 hb = __float2bfloat16(v);
    float lo = v - __bfloat162float(hb);
    int nc = n >> 8, nn = n & 255, kc = k >> 4, kk = k & 15;
    int off = ((nc*16 + kc)*256 + nn)*16 + kk;
    g_w1hi[off] = hb; g_w1lo[off] = __float2bfloat16(lo);
}
__global__ void k_convW2(const float* __restrict__ W2){
    int i = blockIdx.x*256 + threadIdx.x;
    if (i >= 512*256) return;
    int k = i >> 8, n = i & 255;
    float v = W2[(size_t)k*256 + n];
    __nv_bfloat16 hb = __float2bfloat16(v);
    float lo = v - __bfloat162float(hb);
    int kc = k >> 4, kk = k & 15;
    int off = (kc*256 + n)*16 + kk;
    g_w2hi[off] = hb; g_w2lo[off] = __float2bfloat16(lo);
}

// ---------------- fused MLP (R6: ldmatrix + mma.sync, term-major) ----------------
#define AST2 264
#define XST2 520
#define BST  24
#define OFF_AH 0
#define OFF_AL 33792
#define OFF_XH 67584
#define OFF_XL 134144
#define OFF_BH 200704
#define OFF_BL 212992
#define OFF_SC 225280
#define SMEM_TOTAL 229376

__device__ __forceinline__ uint32_t smem_u32(const void* p){
    uint32_t a;
    asm("{ .reg .u64 t; cvta.to.shared.u64 t, %1; cvt.u32.u64 %0, t; }" : "=r"(a) : "l"(p));
    return a;
}
__device__ __forceinline__ void ldmx4(unsigned* r, uint32_t addr){
    asm volatile("ldmatrix.sync.aligned.m8n8.x4.shared.b16 {%0,%1,%2,%3}, [%4];"
        : "=r"(r[0]), "=r"(r[1]), "=r"(r[2]), "=r"(r[3]) : "r"(addr));
}
__device__ __forceinline__ void mma_bf16(float* d, const unsigned* a, unsigned b0, unsigned b1){
    asm volatile(
      "mma.sync.aligned.m16n8k16.row.col.f32.bf16.bf16.f32 "
      "{%0,%1,%2,%3},{%4,%5,%6,%7},{%8,%9},{%0,%1,%2,%3};"
      : "+f"(d[0]), "+f"(d[1]), "+f"(d[2]), "+f"(d[3])
      : "r"(a[0]), "r"(a[1]), "r"(a[2]), "r"(a[3]), "r"(b0), "r"(b1));
}
__device__ __forceinline__ void split2(float x, float y, unsigned &hi, unsigned &lo){
    __nv_bfloat162 h = __floats2bfloat162_rn(x, y);
    float lx = x - __bfloat162float(__low2bfloat16(h));
    float ly = y - __bfloat162float(__high2bfloat16(h));
    __nv_bfloat162 l = __floats2bfloat162_rn(lx, ly);
    hi = *reinterpret_cast<unsigned*>(&h);
    lo = *reinterpret_cast<unsigned*>(&l);
}
__device__ __forceinline__ float2 rec2(unsigned h, unsigned l){
    __nv_bfloat162 hb = *reinterpret_cast<__nv_bfloat162*>(&h);
    __nv_bfloat162 lb = *reinterpret_cast<__nv_bfloat162*>(&l);
    return make_float2(__low2float(hb) + __low2float(lb),
                       __high2float(hb) + __high2float(lb));
}

template<int NK, int ASTRIDE>
__device__ __forceinline__ void gemm_pass(
    uint32_t aHi, uint32_t aLo,
    const __nv_bfloat16* __restrict__ gBh, const __nv_bfloat16* __restrict__ gBl,
    char* sm, uint32_t smb, int tid, int w, float acc[4][4][4])
{
    int lane = tid & 31;
    int arow = lane & 15, akh = (lane >> 4) * 8;
    int brow = (lane & 7) + ((lane >> 4) & 1) * 8;
    int bko  = ((lane >> 3) & 1) * 8;
    int i0 = tid, i1 = tid + 256;
    uint32_t s0 = (uint32_t)(((i0 >> 1)*BST + (i0 & 1)*8)*2);
    uint32_t s1 = (uint32_t)(((i1 >> 1)*BST + (i1 & 1)*8)*2);
    {
        const uint4* ph = (const uint4*)gBh;
        const uint4* pl = (const uint4*)gBl;
        uint4 c0 = ph[i0], c1 = ph[i1], c2 = pl[i0], c3 = pl[i1];
        *(uint4*)(sm + OFF_BH + s0) = c0; *(uint4*)(sm + OFF_BH + s1) = c1;
        *(uint4*)(sm + OFF_BL + s0) = c2; *(uint4*)(sm + OFF_BL + s1) = c3;
    }
    __syncthreads();
    for (int kc = 0; kc < NK; kc++){
        uint4 p0, p1, p2, p3;
        bool pre = (kc + 1 < NK);
        if (pre){
            const uint4* ph = (const uint4*)(gBh + (size_t)(kc+1)*4096);
            const uint4* pl = (const uint4*)(gBl + (size_t)(kc+1)*4096);
            p0 = ph[i0]; p1 = ph[i1]; p2 = pl[i0]; p3 = pl[i1];
        }
        unsigned ah[4][4], al[4][4];
        uint32_t abase = (uint32_t)((arow*ASTRIDE + kc*16 + akh)*2);
        #pragma unroll
        for (int i = 0; i < 4; i++){
            ldmx4(ah[i], aHi + abase + (uint32_t)(i*16*ASTRIDE*2));
            ldmx4(al[i], aLo + abase + (uint32_t)(i*16*ASTRIDE*2));
        }
        unsigned bh[2][4], bl[2][4];
        #pragma unroll
        for (int jj = 0; jj < 2; jj++){
            uint32_t boff = (uint32_t)((((w*32 + jj*16) + brow)*BST + bko)*2);
            ldmx4(bh[jj], smb + OFF_BH + boff);
            ldmx4(bl[jj], smb + OFF_BL + boff);
        }
        // term-major issue order: same-acc MMAs are 16 apart -> no RAW stalls
        #pragma unroll
        for (int t = 0; t < 3; t++){
            #pragma unroll
            for (int j = 0; j < 4; j++){
                unsigned b0 = (t == 1) ? bl[j>>1][(j&1)*2]   : bh[j>>1][(j&1)*2];
                unsigned b1 = (t == 1) ? bl[j>>1][(j&1)*2+1] : bh[j>>1][(j&1)*2+1];
                #pragma unroll
                for (int i = 0; i < 4; i++){
                    mma_bf16(acc[i][j], (t == 2) ? al[i] : ah[i], b0, b1);
                }
            }
        }
        __syncthreads();
        if (pre){
            *(uint4*)(sm + OFF_BH + s0) = p0; *(uint4*)(sm + OFF_BH + s1) = p1;
            *(uint4*)(sm + OFF_BL + s0) = p2; *(uint4*)(sm + OFF_BL + s1) = p3;
            __syncthreads();
        }
    }
}

__global__ void __launch_bounds__(256,1) k_mlp(
    const float* __restrict__ b1v, const float* __restrict__ gamma,
    const float* __restrict__ beta, const float* __restrict__ b2v,
    float* __restrict__ out)
{
    extern __shared__ char sm[];
    uint32_t smb = smem_u32(sm);
    float* SC = (float*)(sm + OFF_SC);

    int tid = threadIdx.x;
    int lane = tid & 31, w = tid >> 5;
    int gid = lane >> 2, tig = lane & 3;
    int rowBase = blockIdx.x * 64;

    // ---- load A tile [64][256], split fp32 -> bf16 hi/lo into smem ----
    for (int i = tid; i < 4096; i += 256){
        int r = i >> 6, c = (i & 63)*4;
        float4 v = *(const float4*)(g_omega + (size_t)(rowBase + r)*256 + c);
        unsigned h0, l0, h1, l1;
        split2(v.x, v.y, h0, l0);
        split2(v.z, v.w, h1, l1);
        *(uint2*)(sm + OFF_AH + (size_t)(r*AST2 + c)*2) = make_uint2(h0, h1);
        *(uint2*)(sm + OFF_AL + (size_t)(r*AST2 + c)*2) = make_uint2(l0, l1);
    }
    __syncthreads();

    float acc[4][4][4];

    // ---- GEMM1: X = A @ W1p, two 256-col chunks, K=256 ----
    for (int nc = 0; nc < 2; nc++){
        #pragma unroll
        for (int i = 0; i < 4; i++)
            #pragma unroll
            for (int j = 0; j < 4; j++)
                #pragma unroll
                for (int q = 0; q < 4; q++) acc[i][j][q] = 0.f;

        gemm_pass<16, AST2>(smb + OFF_AH, smb + OFF_AL,
                            g_w1hi + (size_t)nc*16*4096, g_w1lo + (size_t)nc*16*4096,
                            sm, smb, tid, w, acc);

        #pragma unroll
        for (int j = 0; j < 4; j++){
            int col = nc*256 + w*32 + j*8 + tig*2;
            float ba = __ldg(b1v + col), bb = __ldg(b1v + col + 1);
            #pragma unroll
            for (int i = 0; i < 4; i++){
                int r = i*16 + gid;
                unsigned h, l;
                split2(acc[i][j][0] + ba, acc[i][j][1] + bb, h, l);
                *(unsigned*)(sm + OFF_XH + (size_t)(r*XST2 + col)*2) = h;
                *(unsigned*)(sm + OFF_XL + (size_t)(r*XST2 + col)*2) = l;
                split2(acc[i][j][2] + ba, acc[i][j][3] + bb, h, l);
                *(unsigned*)(sm + OFF_XH + (size_t)((r+8)*XST2 + col)*2) = h;
                *(unsigned*)(sm + OFF_XL + (size_t)((r+8)*XST2 + col)*2) = l;
            }
        }
        __syncthreads();
    }

    // ---- LayerNorm + GELU on X (hi/lo reconstruct, in place) ----
    {
        int r = tid & 63, q = tid >> 6;
        char* xh = sm + OFF_XH + (size_t)(r*XST2 + q*128)*2;
        char* xl = sm + OFF_XL + (size_t)(r*XST2 + q*128)*2;
        float s = 0.f, s2 = 0.f;
        #pragma unroll
        for (int i = 0; i < 16; i++){
            uint4 hv = *(uint4*)(xh + i*16);
            uint4 lv = *(uint4*)(xl + i*16);
            float2 e;
            e = rec2(hv.x, lv.x); s += e.x + e.y; s2 += e.x*e.x + e.y*e.y;
            e = rec2(hv.y, lv.y); s += e.x + e.y; s2 += e.x*e.x + e.y*e.y;
            e = rec2(hv.z, lv.z); s += e.x + e.y; s2 += e.x*e.x + e.y*e.y;
            e = rec2(hv.w, lv.w); s += e.x + e.y; s2 += e.x*e.x + e.y*e.y;
        }
        SC[q*64 + r] = s; SC[256 + q*64 + r] = s2;
        __syncthreads();
        if (tid < 64){
            float S  = SC[tid] + SC[64+tid] + SC[128+tid] + SC[192+tid];
            float S2 = SC[256+tid] + SC[320+tid] + SC[384+tid] + SC[448+tid];
            float mu  = S * (1.f/512.f);
            float var = S2 * (1.f/512.f) - mu*mu;
            SC[512 + tid] = mu;
            SC[576 + tid] = rsqrtf(var + 1e-5f);
        }
        __syncthreads();
        float mu = SC[512 + r], rsg = SC[576 + r];
        #pragma unroll
        for (int i = 0; i < 16; i++){
            uint4 hv = *(uint4*)(xh + i*16);
            uint4 lv = *(uint4*)(xl + i*16);
            unsigned hw[4], lw[4];
            unsigned* hvp = (unsigned*)&hv;
            unsigned* lvp = (unsigned*)&lv;
            #pragma unroll
            for (int t = 0; t < 4; t++){
                float2 e = rec2(hvp[t], lvp[t]);
                int c = q*128 + i*8 + t*2;
                float g0 = __ldg(gamma + c), g1 = __ldg(gamma + c + 1);
                float be0 = __ldg(beta + c), be1 = __ldg(beta + c + 1);
                e.x = (e.x - mu)*rsg*g0 + be0;
                e.y = (e.y - mu)*rsg*g1 + be1;
                e.x = 0.5f*e.x*(1.f + erff(e.x*0.70710678118654752f));
                e.y = 0.5f*e.y*(1.f + erff(e.y*0.70710678118654752f));
                split2(e.x, e.y, hw[t], lw[t]);
            }
            *(uint4*)(xh + i*16) = make_uint4(hw[0], hw[1], hw[2], hw[3]);
            *(uint4*)(xl + i*16) = make_uint4(lw[0], lw[1], lw[2], lw[3]);
        }
        __syncthreads();
    }

    // ---- GEMM2: OUT = X @ W2, one 256-col chunk, K=512 ----
    #pragma unroll
    for (int i = 0; i < 4; i++)
        #pragma unroll
        for (int j = 0; j < 4; j++)
            #pragma unroll
            for (int q = 0; q < 4; q++) acc[i][j][q] = 0.f;

    gemm_pass<32, XST2>(smb + OFF_XH, smb + OFF_XL, g_w2hi, g_w2lo,
                        sm, smb, tid, w, acc);

    #pragma unroll
    for (int j = 0; j < 4; j++){
        int col = w*32 + j*8 + tig*2;
        float ba = __ldg(b2v + col), bb = __ldg(b2v + col + 1);
        #pragma unroll
        for (int i = 0; i < 4; i++){
            int r = i*16 + gid;
            *(float2*)(out + (size_t)(rowBase + r)*256 + col)     = make_float2(acc[i][j][0] + ba, acc[i][j][1] + bb);
            *(float2*)(out + (size_t)(rowBase + r + 8)*256 + col) = make_float2(acc[i][j][2] + ba, acc[i][j][3] + bb);
        }
    }
}

// ---------------- launch ----------------
extern "C" void kernel_launch(void* const* d_in, const int* in_sizes, int n_in,
                              void* d_out, int out_size)
{
    const int* edges = (const int*)d_in[0];
    int p = (in_sizes[1] <= 2) ? 2 : 1;
    const float* poh   = (const float*)d_in[p+0];
    const float* emb   = (const float*)d_in[p+1];
    const float* W1    = (const float*)d_in[p+2];
    const float* b1    = (const float*)d_in[p+3];
    const float* gamma = (const float*)d_in[p+4];
    const float* beta  = (const float*)d_in[p+5];
    const float* W2    = (const float*)d_in[p+6];
    const float* b2    = (const float*)d_in[p+7];
    float* out = (float*)d_out;

    cudaFuncSetAttribute(k_mlp, cudaFuncAttributeMaxDynamicSharedMemorySize, SMEM_TOTAL);

    k_zero_cnt<<<(NROW + 255)/256, 256>>>();
    k_build  <<<(Bg*Eg + 255)/256, 256>>>(edges);
    k_argmax <<<(Nn + 255)/256, 256>>>(poh);
    k_gather <<<(Nn*16 + 255)/256, 256>>>(emb);
    k_convW1 <<<512, 256>>>(W1);
    k_convW2 <<<512, 256>>>(W2);
    for (int h = 1; h <= 4; h++)
        k_hop<<<(NROW*16 + 255)/256, 256>>>(h);
    k_mlp<<<NROW/64, 256, SMEM_TOTAL>>>(b1, gamma, beta, b2, out);
}